// round 7
// baseline (speedup 1.0000x reference)
#include <cuda_runtime.h>
#include <cstddef>

#define BB 4
#define NN 8192
#define CC 128
#define SS 2048
#define KK 32

#define G   8            // CTAs per cluster (per batch), portable max
#define FTC 128          // threads per FPS CTA
#define PPC (NN / G)     // 1024 points per CTA
#define PTT (PPC / FTC)  // 8 points per thread
#define NP2 (PTT / 2)    // 4 packed pairs
#define WPC (FTC / 32)   // 4 warps per CTA
#define NKEYS (G * WPC)  // 32 warp keys per step (one per lane)

typedef unsigned long long u64;

__device__ int g_fps_idx[BB * SS];

// ---- packed f32x2 helpers (each half is an independent IEEE f32 rn op) ----
__device__ __forceinline__ u64 f2add(u64 a, u64 b) {
    u64 d; asm("add.rn.f32x2 %0, %1, %2;" : "=l"(d) : "l"(a), "l"(b)); return d;
}
__device__ __forceinline__ u64 f2mul(u64 a, u64 b) {
    u64 d; asm("mul.rn.f32x2 %0, %1, %2;" : "=l"(d) : "l"(a), "l"(b)); return d;
}
__device__ __forceinline__ u64 f2pack(float lo, float hi) {
    u64 d; asm("mov.b64 %0, {%1, %2};" : "=l"(d) : "f"(lo), "f"(hi)); return d;
}
__device__ __forceinline__ void f2unpack(u64 v, float& lo, float& hi) {
    asm("mov.b64 {%0, %1}, %2;" : "=f"(lo), "=f"(hi) : "l"(v));
}

__device__ __forceinline__ unsigned smem_u32(const void* p) {
    unsigned a;
    asm("{ .reg .u64 t; cvta.to.shared.u64 t, %1; cvt.u32.u64 %0, t; }" : "=r"(a) : "l"(p));
    return a;
}
__device__ __forceinline__ unsigned cluster_rank() {
    unsigned r; asm("mov.u32 %0, %%cluster_ctarank;" : "=r"(r)); return r;
}
__device__ __forceinline__ unsigned mapa_u32(unsigned laddr, unsigned rank) {
    unsigned r; asm("mapa.shared::cluster.u32 %0, %1, %2;" : "=r"(r) : "r"(laddr), "r"(rank));
    return r;
}
// relaxed cluster-scope store: the 64-bit word is the sync token itself
__device__ __forceinline__ void st_cluster_rlx_u64(unsigned addr, u64 v) {
    asm volatile("st.relaxed.cluster.shared::cluster.b64 [%0], %1;"
                 :: "r"(addr), "l"(v) : "memory");
}
__device__ __forceinline__ u64 ld_rlx_u64(unsigned addr) {
    u64 v;
    asm volatile("ld.relaxed.cluster.shared::cta.b64 %0, [%1];"
                 : "=l"(v) : "r"(addr) : "memory");
    return v;
}
__device__ __forceinline__ void cluster_sync() {
    asm volatile("barrier.cluster.arrive.aligned;" ::: "memory");
    asm volatile("barrier.cluster.wait.aligned;" ::: "memory");
}

// ---------------------------------------------------------------------------
// FPS: 8-CTA cluster per batch, 128 threads/CTA, 8 pts/thread in registers.
// Packed f32x2 distance update (bit-exact to scalar unfused form).
// Sync: NO mbarrier. Warp key = (valuebits<<32 | steptag<<16 | index) in one
// aligned b64; lanes 0..7 store it to peer CTA 'lane' mailbox; consumers
// spin-poll their own slot until the embedded tag matches the step. Payload
// and freshness share one word -> no fence/arrive/wakeup. Double-buffered by
// step parity; a slot is overwritten (step s+2) only after every reader
// finished its step-s poll (induction via the s+1 keys), so no lost updates.
// Tags are unique per step (SS < 65536): no false match with stale data.
// ---------------------------------------------------------------------------
__global__ __launch_bounds__(FTC, 1) __cluster_dims__(G, 1, 1)
void fps_kernel(const float* __restrict__ xyz)
{
    const int b = blockIdx.x / G;
    const unsigned r = cluster_rank();
    const int t = threadIdx.x;
    const int lane = t & 31;
    const int w = t >> 5;

    extern __shared__ float4 sxyz[];          // NN float4 (x,y,z,0) -> LDS.128

    __shared__ __align__(8) u64 mbox[2][NKEYS];

    const float* base = xyz + (size_t)b * NN * 3;

    for (int i = t; i < NN; i += FTC) {
        sxyz[i] = make_float4(base[i * 3 + 0], base[i * 3 + 1], base[i * 3 + 2], 0.0f);
    }
    // zero mailbox tags (tag 0 never used: steps start at 1)
    if (t < NKEYS) { mbox[0][t] = 0ull; mbox[1][t] = 0ull; }
    if (t == 0 && r == 0) g_fps_idx[b * SS + 0] = 0;
    __syncthreads();
    cluster_sync();   // tiles + zeroed mailboxes visible before any peer store

    // pack this CTA's slice into registers
    const int gstart = (int)r * PPC + t * PTT;
    u64 pX[NP2], pY[NP2], pZ[NP2];
    float pd[PTT];
#pragma unroll
    for (int jp = 0; jp < NP2; jp++) {
        const int i0 = gstart + 2 * jp;
        const float4 a0 = sxyz[i0];
        const float4 a1 = sxyz[i0 + 1];
        pX[jp] = f2pack(a0.x, a1.x);
        pY[jp] = f2pack(a0.y, a1.y);
        pZ[jp] = f2pack(a0.z, a1.z);
        pd[2 * jp] = 1e10f;
        pd[2 * jp + 1] = 1e10f;
    }

    const unsigned mbox_l    = smem_u32(&mbox[0][0]);
    const unsigned my_slot_l = mbox_l + (unsigned)((r * WPC + w) * sizeof(u64));
    const unsigned bufstride = (unsigned)(sizeof(u64) * NKEYS);

    int far = 0;

    for (int step = 1; step < SS; ++step) {
        const unsigned buf = (unsigned)step & 1u;
        const unsigned tag = (unsigned)step & 0xFFFFu;

        const float4 c = sxyz[far];
        const u64 ncx = f2pack(-c.x, -c.x);
        const u64 ncy = f2pack(-c.y, -c.y);
        const u64 ncz = f2pack(-c.z, -c.z);

#pragma unroll
        for (int jp = 0; jp < NP2; jp++) {
            const u64 dx = f2add(pX[jp], ncx);
            const u64 dy = f2add(pY[jp], ncy);
            const u64 dz = f2add(pZ[jp], ncz);
            const u64 xx = f2mul(dx, dx);
            const u64 yy = f2mul(dy, dy);
            const u64 zz = f2mul(dz, dz);
            const u64 d  = f2add(f2add(xx, yy), zz);
            float dlo, dhi;
            f2unpack(d, dlo, dhi);
            pd[2 * jp]     = fminf(pd[2 * jp],     dlo);
            pd[2 * jp + 1] = fminf(pd[2 * jp + 1], dhi);
        }

        // per-thread max (tree) + first local index achieving it
        float m01[4];
#pragma unroll
        for (int j = 0; j < 4; j++) m01[j] = fmaxf(pd[2 * j], pd[2 * j + 1]);
        const float tv = fmaxf(fmaxf(m01[0], m01[1]), fmaxf(m01[2], m01[3]));

        int bj = PTT - 1;
#pragma unroll
        for (int j = PTT - 2; j >= 0; j--)
            if (pd[j] == tv) bj = j;
        const unsigned gi = (unsigned)(gstart + bj);

        // warp argmax: REDUX max on value bits (monotone, d >= 0),
        // then REDUX min on index among value-ties (= first-index tie-break)
        const unsigned vb = __float_as_uint(tv);
        const unsigned wm = __reduce_max_sync(0xffffffffu, vb);
        const unsigned wi = __reduce_min_sync(0xffffffffu, (vb == wm) ? gi : 0xffffffffu);

        // lanes 0..G-1 broadcast the (warp-uniform) tagged key in parallel
        const u64 key = ((u64)wm << 32) | ((u64)tag << 16) | (u64)wi;
        if (lane < G) {
            st_cluster_rlx_u64(mapa_u32(my_slot_l + buf * bufstride, (unsigned)lane), key);
        }

        // poll own mailbox: lane waits for slot 'lane' to carry this step's tag
        const unsigned pa = mbox_l + buf * bufstride + (unsigned)lane * 8u;
        u64 k = ld_rlx_u64(pa);
        while (((unsigned)(k >> 16) & 0xFFFFu) != tag) k = ld_rlx_u64(pa);

        const unsigned hi = (unsigned)(k >> 32);
        const unsigned bm = __reduce_max_sync(0xffffffffu, hi);
        const unsigned fm = __reduce_min_sync(0xffffffffu,
                                              (hi == bm) ? ((unsigned)k & 0xFFFFu)
                                                         : 0xffffffffu);
        far = (int)fm;

        if (r == 0 && t == 0) g_fps_idx[b * SS + step] = far;
    }
}

// ---------------------------------------------------------------------------
// Fused ball query + grouping + affine + channel max (unchanged, bit-exact).
// ---------------------------------------------------------------------------
__global__ __launch_bounds__(128) void group_kernel(
    const float* __restrict__ xyz,
    const float* __restrict__ points,
    const float* __restrict__ alpha,
    const float* __restrict__ beta,
    float* __restrict__ out_xyz,
    float* __restrict__ out_pts)
{
    const int s = blockIdx.x;
    const int b = blockIdx.y;
    const int tid = threadIdx.x;

    __shared__ int   s_nbr[KK];
    __shared__ int   s_wc[4];
    __shared__ float s_q[3];

    const int fi = g_fps_idx[b * SS + s];
    const float* xb = xyz + (size_t)b * NN * 3;

    if (tid == 0) {
        s_q[0] = xb[fi * 3 + 0];
        s_q[1] = xb[fi * 3 + 1];
        s_q[2] = xb[fi * 3 + 2];
    }
    __syncthreads();

    const float qx = s_q[0], qy = s_q[1], qz = s_q[2];
    const float q2 = __fadd_rn(__fadd_rn(__fmul_rn(qx, qx), __fmul_rn(qy, qy)),
                               __fmul_rn(qz, qz));
    const float RR = 0.04f;   // f32(0.2 * 0.2)

    int cnt = 0;
    const int lane = tid & 31;
    const int w = tid >> 5;

    for (int base2 = 0; base2 < NN && cnt < KK; base2 += 128) {
        const int i = base2 + tid;
        const float xx = xb[i * 3 + 0];
        const float xy = xb[i * 3 + 1];
        const float xz = xb[i * 3 + 2];
        const float x2 = __fadd_rn(__fadd_rn(__fmul_rn(xx, xx), __fmul_rn(xy, xy)),
                                   __fmul_rn(xz, xz));
        const float dt = __fmaf_rn(qz, xz, __fmaf_rn(qy, xy, __fmul_rn(qx, xx)));
        const float sqr = __fsub_rn(__fadd_rn(q2, x2), __fmul_rn(2.0f, dt));
        const bool hit = (sqr <= RR);

        const unsigned m = __ballot_sync(0xffffffffu, hit);
        if (lane == 0) s_wc[w] = __popc(m);
        __syncthreads();

        int before = cnt;
        for (int ww = 0; ww < w; ww++) before += s_wc[ww];
        const int pos = before + __popc(m & ((1u << lane) - 1u));
        if (hit && pos < KK) s_nbr[pos] = i;
        const int tot = s_wc[0] + s_wc[1] + s_wc[2] + s_wc[3];
        __syncthreads();
        cnt += tot;   // uniform across block
    }

    const int cf = (cnt < KK) ? cnt : KK;
    if (tid >= cf && tid < KK) s_nbr[tid] = s_nbr[0];   // pad with first hit
    __syncthreads();

    if (tid < 3) out_xyz[((size_t)b * SS + s) * 3 + tid] = s_q[tid];

    const int c = tid;
    const float a  = alpha[c];
    const float bt = beta[c];
    const float* pb = points + (size_t)b * NN * CC;
    const float anc = pb[(size_t)fi * CC + c];

    float mx = -3.402823466e38f;
#pragma unroll 8
    for (int k = 0; k < KK; k++) {
        const float v = pb[(size_t)s_nbr[k] * CC + c];
        const float g = __fadd_rn(__fmul_rn(a, __fsub_rn(v, anc)), bt);
        mx = fmaxf(mx, g);
    }
    out_pts[((size_t)b * CC + c) * SS + s] = mx;
}

// ---------------------------------------------------------------------------
// Output layout: new_xyz (B,S,3) flat, then new_points (B,C,S) flat.
// ---------------------------------------------------------------------------
extern "C" void kernel_launch(void* const* d_in, const int* in_sizes, int n_in,
                              void* d_out, int out_size)
{
    const float* xyz    = (const float*)d_in[0];
    const float* points = (const float*)d_in[1];
    const float* alpha  = (const float*)d_in[2];
    const float* beta   = (const float*)d_in[3];

    float* out     = (float*)d_out;
    float* out_xyz = out;
    float* out_pts = out + (size_t)BB * SS * 3;

    cudaFuncSetAttribute(fps_kernel, cudaFuncAttributeMaxDynamicSharedMemorySize,
                         NN * (int)sizeof(float4));
    fps_kernel<<<BB * G, FTC, NN * sizeof(float4)>>>(xyz);
    group_kernel<<<dim3(SS, BB), 128>>>(xyz, points, alpha, beta, out_xyz, out_pts);
}

// round 8
// speedup vs baseline: 1.0013x; 1.0013x over previous
#include <cuda_runtime.h>
#include <cstddef>

#define BB 4
#define NN 8192
#define CC 128
#define SS 2048
#define KK 32

#define G   8            // CTAs per cluster (per batch), portable max
#define FTC 128          // threads per FPS CTA
#define PPC (NN / G)     // 1024 points per CTA
#define PTT (PPC / FTC)  // 8 points per thread
#define NP2 (PTT / 2)    // 4 packed pairs
#define WPC (FTC / 32)   // 4 warps per CTA
#define NKEYS (G * WPC)  // 32 warp keys per step (one per lane)

typedef unsigned long long u64;

__device__ int g_fps_idx[BB * SS];

// ---- packed f32x2 helpers (each half is an independent IEEE f32 rn op) ----
__device__ __forceinline__ u64 f2add(u64 a, u64 b) {
    u64 d; asm("add.rn.f32x2 %0, %1, %2;" : "=l"(d) : "l"(a), "l"(b)); return d;
}
__device__ __forceinline__ u64 f2mul(u64 a, u64 b) {
    u64 d; asm("mul.rn.f32x2 %0, %1, %2;" : "=l"(d) : "l"(a), "l"(b)); return d;
}
__device__ __forceinline__ u64 f2pack(float lo, float hi) {
    u64 d; asm("mov.b64 %0, {%1, %2};" : "=l"(d) : "f"(lo), "f"(hi)); return d;
}
__device__ __forceinline__ void f2unpack(u64 v, float& lo, float& hi) {
    asm("mov.b64 {%0, %1}, %2;" : "=f"(lo), "=f"(hi) : "l"(v));
}

__device__ __forceinline__ unsigned smem_u32(const void* p) {
    unsigned a;
    asm("{ .reg .u64 t; cvta.to.shared.u64 t, %1; cvt.u32.u64 %0, t; }" : "=r"(a) : "l"(p));
    return a;
}
__device__ __forceinline__ unsigned cluster_rank() {
    unsigned r; asm("mov.u32 %0, %%cluster_ctarank;" : "=r"(r)); return r;
}
__device__ __forceinline__ unsigned mapa_u32(unsigned laddr, unsigned rank) {
    unsigned r; asm("mapa.shared::cluster.u32 %0, %1, %2;" : "=r"(r) : "r"(laddr), "r"(rank));
    return r;
}
// relaxed cluster-scope store: the 64-bit word is the sync token itself
__device__ __forceinline__ void st_cluster_rlx_u64(unsigned addr, u64 v) {
    asm volatile("st.relaxed.cluster.shared::cluster.b64 [%0], %1;"
                 :: "r"(addr), "l"(v) : "memory");
}
// LOCAL volatile poll — 29-cy LDS path (R7 bug: .relaxed.cluster load took the
// ~200-cy cluster-fabric path for a local address)
__device__ __forceinline__ u64 lds_volatile_u64(unsigned addr) {
    u64 v;
    asm volatile("ld.volatile.shared.b64 %0, [%1];" : "=l"(v) : "r"(addr) : "memory");
    return v;
}
__device__ __forceinline__ void cluster_sync() {
    asm volatile("barrier.cluster.arrive.aligned;" ::: "memory");
    asm volatile("barrier.cluster.wait.aligned;" ::: "memory");
}

// ---------------------------------------------------------------------------
// FPS: 8-CTA cluster per batch, 128 threads/CTA, 8 pts/thread in registers.
// Packed f32x2 distance update (bit-exact to scalar unfused form).
// Sync: tagged mailboxes, NO mbarrier. Warp key =
// (valuebits<<32 | steptag<<16 | index) in one aligned b64; lanes 0..7 store
// it to peer CTA 'lane'; consumers poll their OWN slot with volatile LDS
// until the embedded tag matches. Payload and freshness share one atomic
// 64-bit word -> no fence/arrive/wakeup, and a stale read just spins once
// more. Double-buffered by parity: slot for step s+2 is written only after
// the writer finished its step-s poll of all slots (induction via s+1 keys),
// so readers are never lapped. Tags unique per step (SS < 65536).
// ---------------------------------------------------------------------------
__global__ __launch_bounds__(FTC, 1) __cluster_dims__(G, 1, 1)
void fps_kernel(const float* __restrict__ xyz)
{
    const int b = blockIdx.x / G;
    const unsigned r = cluster_rank();
    const int t = threadIdx.x;
    const int lane = t & 31;
    const int w = t >> 5;

    extern __shared__ float4 sxyz[];          // NN float4 (x,y,z,0) -> LDS.128

    __shared__ __align__(8) u64 mbox[2][NKEYS];

    const float* base = xyz + (size_t)b * NN * 3;

    for (int i = t; i < NN; i += FTC) {
        sxyz[i] = make_float4(base[i * 3 + 0], base[i * 3 + 1], base[i * 3 + 2], 0.0f);
    }
    // zero mailbox tags (tag 0 never used: steps start at 1)
    if (t < NKEYS) { mbox[0][t] = 0ull; mbox[1][t] = 0ull; }
    if (t == 0 && r == 0) g_fps_idx[b * SS + 0] = 0;
    __syncthreads();
    cluster_sync();   // tiles + zeroed mailboxes visible before any peer store

    // pack this CTA's slice into registers
    const int gstart = (int)r * PPC + t * PTT;
    u64 pX[NP2], pY[NP2], pZ[NP2];
    float pd[PTT];
#pragma unroll
    for (int jp = 0; jp < NP2; jp++) {
        const int i0 = gstart + 2 * jp;
        const float4 a0 = sxyz[i0];
        const float4 a1 = sxyz[i0 + 1];
        pX[jp] = f2pack(a0.x, a1.x);
        pY[jp] = f2pack(a0.y, a1.y);
        pZ[jp] = f2pack(a0.z, a1.z);
        pd[2 * jp] = 1e10f;
        pd[2 * jp + 1] = 1e10f;
    }

    const unsigned mbox_l    = smem_u32(&mbox[0][0]);
    const unsigned my_slot_l = mbox_l + (unsigned)((r * WPC + w) * sizeof(u64));
    const unsigned bufstride = (unsigned)(sizeof(u64) * NKEYS);

    int far = 0;

    for (int step = 1; step < SS; ++step) {
        const unsigned buf = (unsigned)step & 1u;
        const unsigned tag = (unsigned)step & 0xFFFFu;

        const float4 c = sxyz[far];
        const u64 ncx = f2pack(-c.x, -c.x);
        const u64 ncy = f2pack(-c.y, -c.y);
        const u64 ncz = f2pack(-c.z, -c.z);

#pragma unroll
        for (int jp = 0; jp < NP2; jp++) {
            const u64 dx = f2add(pX[jp], ncx);
            const u64 dy = f2add(pY[jp], ncy);
            const u64 dz = f2add(pZ[jp], ncz);
            const u64 xx = f2mul(dx, dx);
            const u64 yy = f2mul(dy, dy);
            const u64 zz = f2mul(dz, dz);
            const u64 d  = f2add(f2add(xx, yy), zz);
            float dlo, dhi;
            f2unpack(d, dlo, dhi);
            pd[2 * jp]     = fminf(pd[2 * jp],     dlo);
            pd[2 * jp + 1] = fminf(pd[2 * jp + 1], dhi);
        }

        // per-thread max (tree) + first local index achieving it
        float m01[4];
#pragma unroll
        for (int j = 0; j < 4; j++) m01[j] = fmaxf(pd[2 * j], pd[2 * j + 1]);
        const float tv = fmaxf(fmaxf(m01[0], m01[1]), fmaxf(m01[2], m01[3]));

        int bj = PTT - 1;
#pragma unroll
        for (int j = PTT - 2; j >= 0; j--)
            if (pd[j] == tv) bj = j;
        const unsigned gi = (unsigned)(gstart + bj);

        // warp argmax: REDUX max on value bits (monotone, d >= 0),
        // then REDUX min on index among value-ties (= first-index tie-break)
        const unsigned vb = __float_as_uint(tv);
        const unsigned wm = __reduce_max_sync(0xffffffffu, vb);
        const unsigned wi = __reduce_min_sync(0xffffffffu, (vb == wm) ? gi : 0xffffffffu);

        // lanes 0..G-1 broadcast the (warp-uniform) tagged key in parallel
        const u64 key = ((u64)wm << 32) | ((u64)tag << 16) | (u64)wi;
        if (lane < G) {
            st_cluster_rlx_u64(mapa_u32(my_slot_l + buf * bufstride, (unsigned)lane), key);
        }

        // poll own mailbox slot (LOCAL volatile LDS, 29 cy/iter)
        const unsigned pa = mbox_l + buf * bufstride + (unsigned)lane * 8u;
        u64 k = lds_volatile_u64(pa);
        while (((unsigned)(k >> 16) & 0xFFFFu) != tag) k = lds_volatile_u64(pa);

        const unsigned hi = (unsigned)(k >> 32);
        const unsigned bm = __reduce_max_sync(0xffffffffu, hi);
        const unsigned fm = __reduce_min_sync(0xffffffffu,
                                              (hi == bm) ? ((unsigned)k & 0xFFFFu)
                                                         : 0xffffffffu);
        far = (int)fm;

        if (r == 0 && t == 0) g_fps_idx[b * SS + step] = far;
    }
}

// ---------------------------------------------------------------------------
// Fused ball query + grouping + affine + channel max (unchanged, bit-exact).
// ---------------------------------------------------------------------------
__global__ __launch_bounds__(128) void group_kernel(
    const float* __restrict__ xyz,
    const float* __restrict__ points,
    const float* __restrict__ alpha,
    const float* __restrict__ beta,
    float* __restrict__ out_xyz,
    float* __restrict__ out_pts)
{
    const int s = blockIdx.x;
    const int b = blockIdx.y;
    const int tid = threadIdx.x;

    __shared__ int   s_nbr[KK];
    __shared__ int   s_wc[4];
    __shared__ float s_q[3];

    const int fi = g_fps_idx[b * SS + s];
    const float* xb = xyz + (size_t)b * NN * 3;

    if (tid == 0) {
        s_q[0] = xb[fi * 3 + 0];
        s_q[1] = xb[fi * 3 + 1];
        s_q[2] = xb[fi * 3 + 2];
    }
    __syncthreads();

    const float qx = s_q[0], qy = s_q[1], qz = s_q[2];
    const float q2 = __fadd_rn(__fadd_rn(__fmul_rn(qx, qx), __fmul_rn(qy, qy)),
                               __fmul_rn(qz, qz));
    const float RR = 0.04f;   // f32(0.2 * 0.2)

    int cnt = 0;
    const int lane = tid & 31;
    const int w = tid >> 5;

    for (int base2 = 0; base2 < NN && cnt < KK; base2 += 128) {
        const int i = base2 + tid;
        const float xx = xb[i * 3 + 0];
        const float xy = xb[i * 3 + 1];
        const float xz = xb[i * 3 + 2];
        const float x2 = __fadd_rn(__fadd_rn(__fmul_rn(xx, xx), __fmul_rn(xy, xy)),
                                   __fmul_rn(xz, xz));
        const float dt = __fmaf_rn(qz, xz, __fmaf_rn(qy, xy, __fmul_rn(qx, xx)));
        const float sqr = __fsub_rn(__fadd_rn(q2, x2), __fmul_rn(2.0f, dt));
        const bool hit = (sqr <= RR);

        const unsigned m = __ballot_sync(0xffffffffu, hit);
        if (lane == 0) s_wc[w] = __popc(m);
        __syncthreads();

        int before = cnt;
        for (int ww = 0; ww < w; ww++) before += s_wc[ww];
        const int pos = before + __popc(m & ((1u << lane) - 1u));
        if (hit && pos < KK) s_nbr[pos] = i;
        const int tot = s_wc[0] + s_wc[1] + s_wc[2] + s_wc[3];
        __syncthreads();
        cnt += tot;   // uniform across block
    }

    const int cf = (cnt < KK) ? cnt : KK;
    if (tid >= cf && tid < KK) s_nbr[tid] = s_nbr[0];   // pad with first hit
    __syncthreads();

    if (tid < 3) out_xyz[((size_t)b * SS + s) * 3 + tid] = s_q[tid];

    const int c = tid;
    const float a  = alpha[c];
    const float bt = beta[c];
    const float* pb = points + (size_t)b * NN * CC;
    const float anc = pb[(size_t)fi * CC + c];

    float mx = -3.402823466e38f;
#pragma unroll 8
    for (int k = 0; k < KK; k++) {
        const float v = pb[(size_t)s_nbr[k] * CC + c];
        const float g = __fadd_rn(__fmul_rn(a, __fsub_rn(v, anc)), bt);
        mx = fmaxf(mx, g);
    }
    out_pts[((size_t)b * CC + c) * SS + s] = mx;
}

// ---------------------------------------------------------------------------
// Output layout: new_xyz (B,S,3) flat, then new_points (B,C,S) flat.
// ---------------------------------------------------------------------------
extern "C" void kernel_launch(void* const* d_in, const int* in_sizes, int n_in,
                              void* d_out, int out_size)
{
    const float* xyz    = (const float*)d_in[0];
    const float* points = (const float*)d_in[1];
    const float* alpha  = (const float*)d_in[2];
    const float* beta   = (const float*)d_in[3];

    float* out     = (float*)d_out;
    float* out_xyz = out;
    float* out_pts = out + (size_t)BB * SS * 3;

    cudaFuncSetAttribute(fps_kernel, cudaFuncAttributeMaxDynamicSharedMemorySize,
                         NN * (int)sizeof(float4));
    fps_kernel<<<BB * G, FTC, NN * sizeof(float4)>>>(xyz);
    group_kernel<<<dim3(SS, BB), 128>>>(xyz, points, alpha, beta, out_xyz, out_pts);
}